// round 3
// baseline (speedup 1.0000x reference)
#include <cuda_runtime.h>
#include <math.h>
#include <math_constants.h>

#define NN 50000
#define EE 640000
#define DIN 256
#define DD 128
#define HH 8
#define NCC 47
#define LL 3

// ---------------- scratch (static device allocations; no runtime alloc) ----
__device__ float g_h[NN * DD];        // node features
__device__ float g_q[NN * DD];
__device__ float g_k[NN * DD];
__device__ float g_v[NN * DD];
__device__ float g_agg[NN * DD];
__device__ float g_t[NN * 512];       // tmp: pre-LN embed [N,128], agg@Wo [N,128], ff1 [N,512]
__device__ float g_t2[NN * 512];      // ff2 [N,512]
__device__ int   g_deg[NN];
__device__ int   g_off[NN + 1];
__device__ int   g_cur[NN];
__device__ int   g_csr[EE];

// ---------------- CSR build ------------------------------------------------
__global__ void zero_deg_kernel() {
    int i = blockIdx.x * blockDim.x + threadIdx.x;
    if (i < NN) g_deg[i] = 0;
}

__global__ void count_deg_kernel(const int* __restrict__ dst) {
    int e = blockIdx.x * blockDim.x + threadIdx.x;
    if (e < EE) atomicAdd(&g_deg[dst[e]], 1);
}

// Single-block exclusive scan over g_deg -> g_off, g_cur (warp-shuffle based)
__global__ void scan_kernel() {
    __shared__ int wsum[32];
    __shared__ int carry_s;
    int t = threadIdx.x, lane = t & 31, wid = t >> 5;
    if (t == 0) carry_s = 0;
    __syncthreads();
    for (int base = 0; base < NN; base += 1024) {
        int i = base + t;
        int val = (i < NN) ? g_deg[i] : 0;
        int incl = val;
        #pragma unroll
        for (int o = 1; o < 32; o <<= 1) {
            int x = __shfl_up_sync(0xFFFFFFFFu, incl, o);
            if (lane >= o) incl += x;
        }
        if (lane == 31) wsum[wid] = incl;
        __syncthreads();
        if (wid == 0) {
            int wv = wsum[lane];
            int wincl = wv;
            #pragma unroll
            for (int o = 1; o < 32; o <<= 1) {
                int x = __shfl_up_sync(0xFFFFFFFFu, wincl, o);
                if (lane >= o) wincl += x;
            }
            wsum[lane] = wincl - wv;  // exclusive warp prefix
        }
        __syncthreads();
        int carry = carry_s;
        int excl = carry + wsum[wid] + incl - val;
        if (i < NN) { g_off[i] = excl; g_cur[i] = excl; }
        __syncthreads();
        if (t == 1023) carry_s = carry + wsum[31] + incl;
        __syncthreads();
    }
    if (threadIdx.x == 0) g_off[NN] = carry_s;
}

__global__ void scatter_kernel(const int* __restrict__ src, const int* __restrict__ dst) {
    int e = blockIdx.x * blockDim.x + threadIdx.x;
    if (e < EE) {
        int d = dst[e];
        int pos = atomicAdd(&g_cur[d], 1);
        g_csr[pos] = src[e];
    }
}

// ---------------- SGEMM: C[M,N] = A[M,K] @ B[K,N] (+bias, relu) ------------
// BM=BN=128, BK=8, 256 threads, 8x8 microtile per thread.
template <int BIAS, int RELU>
__global__ void sgemm_kernel(const float* __restrict__ A, const float* __restrict__ B,
                             const float* __restrict__ bias, float* __restrict__ C,
                             int M, int N, int K) {
    __shared__ float As[8][128];
    __shared__ float Bs[8][128];
    int tid = threadIdx.x;
    int row0 = blockIdx.y * 128, col0 = blockIdx.x * 128;
    int tx = tid & 15, ty = tid >> 4;
    int aRow = tid >> 1, aSeg = tid & 1;
    int bRow = tid >> 5, bCol4 = tid & 31;
    float acc[8][8];
    #pragma unroll
    for (int i = 0; i < 8; i++)
        #pragma unroll
        for (int j = 0; j < 8; j++) acc[i][j] = 0.f;

    const bool nVec = ((N & 127) == 0);  // full-width column tiles: vector loads safe

    for (int k0 = 0; k0 < K; k0 += 8) {
        // A tile (128 rows x 8 k), transposed store
        {
            int gr = row0 + aRow;
            float4 va = make_float4(0.f, 0.f, 0.f, 0.f);
            if (gr < M) va = *(const float4*)(A + (size_t)gr * K + k0 + aSeg * 4);
            As[aSeg * 4 + 0][aRow] = va.x;
            As[aSeg * 4 + 1][aRow] = va.y;
            As[aSeg * 4 + 2][aRow] = va.z;
            As[aSeg * 4 + 3][aRow] = va.w;
        }
        // B tile (8 k x 128 cols)
        {
            int gc = col0 + bCol4 * 4;
            const float* bp = B + (size_t)(k0 + bRow) * N + gc;
            float4 vb;
            if (nVec) {
                vb = *(const float4*)bp;
            } else {
                vb.x = (gc + 0 < N) ? bp[0] : 0.f;
                vb.y = (gc + 1 < N) ? bp[1] : 0.f;
                vb.z = (gc + 2 < N) ? bp[2] : 0.f;
                vb.w = (gc + 3 < N) ? bp[3] : 0.f;
            }
            *(float4*)&Bs[bRow][bCol4 * 4] = vb;
        }
        __syncthreads();
        #pragma unroll
        for (int kk = 0; kk < 8; kk++) {
            float a[8], b[8];
            #pragma unroll
            for (int i = 0; i < 8; i++) a[i] = As[kk][ty * 8 + i];
            #pragma unroll
            for (int j = 0; j < 8; j++) b[j] = Bs[kk][tx * 8 + j];
            #pragma unroll
            for (int i = 0; i < 8; i++)
                #pragma unroll
                for (int j = 0; j < 8; j++)
                    acc[i][j] = fmaf(a[i], b[j], acc[i][j]);
        }
        __syncthreads();
    }

    #pragma unroll
    for (int i = 0; i < 8; i++) {
        int r = row0 + ty * 8 + i;
        if (r >= M) break;
        #pragma unroll
        for (int j = 0; j < 8; j++) {
            int c = col0 + tx * 8 + j;
            if (c < N) {
                float val = acc[i][j];
                if (BIAS) val += bias[c];
                if (RELU) val = fmaxf(val, 0.f);
                C[(size_t)r * N + c] = val;
            }
        }
    }
}

// ---------------- LayerNorm over D=128 (warp per node) ---------------------
template <int RESID>
__global__ void ln_kernel(const float* __restrict__ X, const float* __restrict__ R,
                          const float* __restrict__ g, const float* __restrict__ b,
                          float* __restrict__ out) {
    int node = blockIdx.x * (blockDim.x >> 5) + (threadIdx.x >> 5);
    if (node >= NN) return;
    int lane = threadIdx.x & 31;
    float4 x = ((const float4*)(X + (size_t)node * DD))[lane];
    if (RESID) {
        float4 r = ((const float4*)(R + (size_t)node * DD))[lane];
        x.x += r.x; x.y += r.y; x.z += r.z; x.w += r.w;
    }
    float s = x.x + x.y + x.z + x.w;
    #pragma unroll
    for (int o = 16; o; o >>= 1) s += __shfl_xor_sync(0xFFFFFFFFu, s, o);
    float mu = s * (1.f / 128.f);
    float dx = x.x - mu, dy = x.y - mu, dz = x.z - mu, dw = x.w - mu;
    float v = dx * dx + dy * dy + dz * dz + dw * dw;
    #pragma unroll
    for (int o = 16; o; o >>= 1) v += __shfl_xor_sync(0xFFFFFFFFu, v, o);
    float rstd = rsqrtf(v * (1.f / 128.f) + 1e-5f);
    float4 gg = ((const float4*)g)[lane];
    float4 bb = ((const float4*)b)[lane];
    float4 o4;
    o4.x = dx * rstd * gg.x + bb.x;
    o4.y = dy * rstd * gg.y + bb.y;
    o4.z = dz * rstd * gg.z + bb.z;
    o4.w = dw * rstd * gg.w + bb.w;
    ((float4*)(out + (size_t)node * DD))[lane] = o4;
}

// ---------------- attention + aggregation (warp per dst node) --------------
// lane covers dims [4*lane, 4*lane+4); head = lane/4 (DH=16 -> 4 lanes/head).
__global__ void attn_kernel() {
    int node = blockIdx.x * (blockDim.x >> 5) + (threadIdx.x >> 5);
    if (node >= NN) return;
    int lane = threadIdx.x & 31;
    float4 qv = ((const float4*)(g_q + (size_t)node * DD))[lane];
    float m = -CUDART_INF_F, s = 0.f;
    float4 acc = make_float4(0.f, 0.f, 0.f, 0.f);
    int e0 = g_off[node], e1 = g_off[node + 1];
    for (int e = e0; e < e1; e++) {
        int src = g_csr[e];
        float4 kv = ((const float4*)(g_k + (size_t)src * DD))[lane];
        float4 vv = ((const float4*)(g_v + (size_t)src * DD))[lane];
        float p = qv.x * kv.x + qv.y * kv.y + qv.z * kv.z + qv.w * kv.w;
        p += __shfl_xor_sync(0xFFFFFFFFu, p, 1);
        p += __shfl_xor_sync(0xFFFFFFFFu, p, 2);
        float score = p * 0.25f;  // 1/sqrt(DH=16)
        float mnew = fmaxf(m, score);
        float f = __expf(m - mnew);     // 0 on first edge (m = -inf)
        float w = __expf(score - mnew);
        s = s * f + w;
        acc.x = acc.x * f + w * vv.x;
        acc.y = acc.y * f + w * vv.y;
        acc.z = acc.z * f + w * vv.z;
        acc.w = acc.w * f + w * vv.w;
        m = mnew;
    }
    float inv = (s > 0.f) ? 1.f / s : 0.f;
    float4 o = make_float4(acc.x * inv, acc.y * inv, acc.z * inv, acc.w * inv);
    ((float4*)(g_agg + (size_t)node * DD))[lane] = o;
}

// ---------------- host-side launch -----------------------------------------
static inline void run_gemm(int bias, int relu, const float* A, const float* B,
                            const float* bp, float* C, int M, int N, int K) {
    dim3 grid((N + 127) / 128, (M + 127) / 128);
    if (bias && relu)      sgemm_kernel<1, 1><<<grid, 256>>>(A, B, bp, C, M, N, K);
    else if (bias)         sgemm_kernel<1, 0><<<grid, 256>>>(A, B, bp, C, M, N, K);
    else                   sgemm_kernel<0, 0><<<grid, 256>>>(A, B, bp, C, M, N, K);
}

extern "C" void kernel_launch(void* const* d_in, const int* in_sizes, int n_in,
                              void* d_out, int out_size) {
    const float* X        = (const float*)d_in[0];
    const int*   ei       = (const int*)d_in[1];
    const float* emb_w    = (const float*)d_in[2];
    const float* emb_b    = (const float*)d_in[3];
    const float* emb_ln_g = (const float*)d_in[4];
    const float* emb_ln_b = (const float*)d_in[5];
    const float* Wq       = (const float*)d_in[6];
    const float* Wk       = (const float*)d_in[7];
    const float* Wv       = (const float*)d_in[8];
    const float* Wo       = (const float*)d_in[9];
    const float* ln_g     = (const float*)d_in[10];
    const float* ln_b     = (const float*)d_in[11];
    const float* f1_w     = (const float*)d_in[12];
    const float* f1_b     = (const float*)d_in[13];
    const float* f2_w     = (const float*)d_in[14];
    const float* f2_b     = (const float*)d_in[15];
    const float* f3_w     = (const float*)d_in[16];
    const float* f3_b     = (const float*)d_in[17];
    float* out = (float*)d_out;

    const int* src = ei;
    const int* dst = ei + EE;

    float *p_h, *p_q, *p_k, *p_v, *p_agg, *p_t, *p_t2;
    cudaGetSymbolAddress((void**)&p_h,   g_h);
    cudaGetSymbolAddress((void**)&p_q,   g_q);
    cudaGetSymbolAddress((void**)&p_k,   g_k);
    cudaGetSymbolAddress((void**)&p_v,   g_v);
    cudaGetSymbolAddress((void**)&p_agg, g_agg);
    cudaGetSymbolAddress((void**)&p_t,   g_t);
    cudaGetSymbolAddress((void**)&p_t2,  g_t2);

    // ---- CSR build (by dst) ----
    zero_deg_kernel<<<(NN + 255) / 256, 256>>>();
    count_deg_kernel<<<(EE + 255) / 256, 256>>>(dst);
    scan_kernel<<<1, 1024>>>();
    scatter_kernel<<<(EE + 255) / 256, 256>>>(src, dst);

    // ---- embedding: relu(X @ emb_w + b) -> LN -> h ----
    run_gemm(1, 1, X, emb_w, emb_b, p_t, NN, DD, DIN);
    ln_kernel<0><<<(NN + 7) / 8, 256>>>(p_t, nullptr, emb_ln_g, emb_ln_b, p_h);

    // ---- layers ----
    for (int l = 0; l < LL; l++) {
        const float* wq = Wq + (size_t)l * DD * DD;
        const float* wk = Wk + (size_t)l * DD * DD;
        const float* wv = Wv + (size_t)l * DD * DD;
        const float* wo = Wo + (size_t)l * DD * DD;
        run_gemm(0, 0, p_h, wq, nullptr, p_q, NN, DD, DD);
        run_gemm(0, 0, p_h, wk, nullptr, p_k, NN, DD, DD);
        run_gemm(0, 0, p_h, wv, nullptr, p_v, NN, DD, DD);
        attn_kernel<<<(NN + 7) / 8, 256>>>();
        run_gemm(0, 0, p_agg, wo, nullptr, p_t, NN, DD, DD);
        ln_kernel<1><<<(NN + 7) / 8, 256>>>(p_t, p_h, ln_g + l * DD, ln_b + l * DD, p_h);
    }

    // ---- MLP head ----
    run_gemm(1, 1, p_h,  f1_w, f1_b, p_t,  NN, 512, DD);
    run_gemm(1, 1, p_t,  f2_w, f2_b, p_t2, NN, 512, 512);
    run_gemm(1, 0, p_t2, f3_w, f3_b, out,  NN, NCC, 512);
}

// round 4
// speedup vs baseline: 1.0011x; 1.0011x over previous
#include <cuda_runtime.h>
#include <math.h>
#include <math_constants.h>

#define NN 50000
#define EE 640000
#define DIN 256
#define DD 128
#define HH 8
#define NCC 47
#define LL 3

// ---------------- scratch (static device allocations; no runtime alloc) ----
__device__ float g_h[NN * DD];        // node features
__device__ float g_q[NN * DD];
__device__ float g_k[NN * DD];
__device__ float g_v[NN * DD];
__device__ float g_agg[NN * DD];
__device__ float g_t[NN * 512];       // tmp: pre-LN embed [N,128], agg@Wo [N,128], ff1 [N,512]
__device__ float g_t2[NN * 512];      // ff2 [N,512]
__device__ int   g_deg[NN];
__device__ int   g_off[NN + 1];
__device__ int   g_cur[NN];
__device__ int   g_csr[EE];

// ---------------- CSR build ------------------------------------------------
__global__ void zero_deg_kernel() {
    int i = blockIdx.x * blockDim.x + threadIdx.x;
    if (i < NN) g_deg[i] = 0;
}

__global__ void count_deg_kernel(const int* __restrict__ dst) {
    int e = blockIdx.x * blockDim.x + threadIdx.x;
    if (e < EE) atomicAdd(&g_deg[dst[e]], 1);
}

// Single-block exclusive scan over g_deg -> g_off, g_cur (warp-shuffle based)
__global__ void scan_kernel() {
    __shared__ int wsum[32];
    __shared__ int carry_s;
    int t = threadIdx.x, lane = t & 31, wid = t >> 5;
    if (t == 0) carry_s = 0;
    __syncthreads();
    for (int base = 0; base < NN; base += 1024) {
        int i = base + t;
        int val = (i < NN) ? g_deg[i] : 0;
        int incl = val;
        #pragma unroll
        for (int o = 1; o < 32; o <<= 1) {
            int x = __shfl_up_sync(0xFFFFFFFFu, incl, o);
            if (lane >= o) incl += x;
        }
        if (lane == 31) wsum[wid] = incl;
        __syncthreads();
        if (wid == 0) {
            int wv = wsum[lane];
            int wincl = wv;
            #pragma unroll
            for (int o = 1; o < 32; o <<= 1) {
                int x = __shfl_up_sync(0xFFFFFFFFu, wincl, o);
                if (lane >= o) wincl += x;
            }
            wsum[lane] = wincl - wv;  // exclusive warp prefix
        }
        __syncthreads();
        int carry = carry_s;
        int excl = carry + wsum[wid] + incl - val;
        if (i < NN) { g_off[i] = excl; g_cur[i] = excl; }
        __syncthreads();
        if (t == 1023) carry_s = carry + wsum[31] + incl;
        __syncthreads();
    }
    if (threadIdx.x == 0) g_off[NN] = carry_s;
}

__global__ void scatter_kernel(const int* __restrict__ src, const int* __restrict__ dst) {
    int e = blockIdx.x * blockDim.x + threadIdx.x;
    if (e < EE) {
        int d = dst[e];
        int pos = atomicAdd(&g_cur[d], 1);
        g_csr[pos] = src[e];
    }
}

// ---------------- SGEMM: C[M,N] = A[M,K] @ B[K,N] (+bias, relu) ------------
// BM=BN=128, BK=8, 256 threads, 8x8 microtile per thread.
template <int BIAS, int RELU>
__global__ void sgemm_kernel(const float* __restrict__ A, const float* __restrict__ B,
                             const float* __restrict__ bias, float* __restrict__ C,
                             int M, int N, int K) {
    __shared__ float As[8][128];
    __shared__ float Bs[8][128];
    int tid = threadIdx.x;
    int row0 = blockIdx.y * 128, col0 = blockIdx.x * 128;
    int tx = tid & 15, ty = tid >> 4;
    int aRow = tid >> 1, aSeg = tid & 1;
    int bRow = tid >> 5, bCol4 = tid & 31;
    float acc[8][8];
    #pragma unroll
    for (int i = 0; i < 8; i++)
        #pragma unroll
        for (int j = 0; j < 8; j++) acc[i][j] = 0.f;

    const bool nVec = ((N & 127) == 0);  // full-width column tiles: vector loads safe

    for (int k0 = 0; k0 < K; k0 += 8) {
        // A tile (128 rows x 8 k), transposed store
        {
            int gr = row0 + aRow;
            float4 va = make_float4(0.f, 0.f, 0.f, 0.f);
            if (gr < M) va = *(const float4*)(A + (size_t)gr * K + k0 + aSeg * 4);
            As[aSeg * 4 + 0][aRow] = va.x;
            As[aSeg * 4 + 1][aRow] = va.y;
            As[aSeg * 4 + 2][aRow] = va.z;
            As[aSeg * 4 + 3][aRow] = va.w;
        }
        // B tile (8 k x 128 cols)
        {
            int gc = col0 + bCol4 * 4;
            const float* bp = B + (size_t)(k0 + bRow) * N + gc;
            float4 vb;
            if (nVec) {
                vb = *(const float4*)bp;
            } else {
                vb.x = (gc + 0 < N) ? bp[0] : 0.f;
                vb.y = (gc + 1 < N) ? bp[1] : 0.f;
                vb.z = (gc + 2 < N) ? bp[2] : 0.f;
                vb.w = (gc + 3 < N) ? bp[3] : 0.f;
            }
            *(float4*)&Bs[bRow][bCol4 * 4] = vb;
        }
        __syncthreads();
        #pragma unroll
        for (int kk = 0; kk < 8; kk++) {
            float a[8], b[8];
            #pragma unroll
            for (int i = 0; i < 8; i++) a[i] = As[kk][ty * 8 + i];
            #pragma unroll
            for (int j = 0; j < 8; j++) b[j] = Bs[kk][tx * 8 + j];
            #pragma unroll
            for (int i = 0; i < 8; i++)
                #pragma unroll
                for (int j = 0; j < 8; j++)
                    acc[i][j] = fmaf(a[i], b[j], acc[i][j]);
        }
        __syncthreads();
    }

    #pragma unroll
    for (int i = 0; i < 8; i++) {
        int r = row0 + ty * 8 + i;
        if (r >= M) break;
        #pragma unroll
        for (int j = 0; j < 8; j++) {
            int c = col0 + tx * 8 + j;
            if (c < N) {
                float val = acc[i][j];
                if (BIAS) val += bias[c];
                if (RELU) val = fmaxf(val, 0.f);
                C[(size_t)r * N + c] = val;
            }
        }
    }
}

// ---------------- LayerNorm over D=128 (warp per node) ---------------------
template <int RESID>
__global__ void ln_kernel(const float* __restrict__ X, const float* __restrict__ R,
                          const float* __restrict__ g, const float* __restrict__ b,
                          float* __restrict__ out) {
    int node = blockIdx.x * (blockDim.x >> 5) + (threadIdx.x >> 5);
    if (node >= NN) return;
    int lane = threadIdx.x & 31;
    float4 x = ((const float4*)(X + (size_t)node * DD))[lane];
    if (RESID) {
        float4 r = ((const float4*)(R + (size_t)node * DD))[lane];
        x.x += r.x; x.y += r.y; x.z += r.z; x.w += r.w;
    }
    float s = x.x + x.y + x.z + x.w;
    #pragma unroll
    for (int o = 16; o; o >>= 1) s += __shfl_xor_sync(0xFFFFFFFFu, s, o);
    float mu = s * (1.f / 128.f);
    float dx = x.x - mu, dy = x.y - mu, dz = x.z - mu, dw = x.w - mu;
    float v = dx * dx + dy * dy + dz * dz + dw * dw;
    #pragma unroll
    for (int o = 16; o; o >>= 1) v += __shfl_xor_sync(0xFFFFFFFFu, v, o);
    float rstd = rsqrtf(v * (1.f / 128.f) + 1e-5f);
    float4 gg = ((const float4*)g)[lane];
    float4 bb = ((const float4*)b)[lane];
    float4 o4;
    o4.x = dx * rstd * gg.x + bb.x;
    o4.y = dy * rstd * gg.y + bb.y;
    o4.z = dz * rstd * gg.z + bb.z;
    o4.w = dw * rstd * gg.w + bb.w;
    ((float4*)(out + (size_t)node * DD))[lane] = o4;
}

// ---------------- attention + aggregation (warp per dst node) --------------
// lane covers dims [4*lane, 4*lane+4); head = lane/4 (DH=16 -> 4 lanes/head).
__global__ void attn_kernel() {
    int node = blockIdx.x * (blockDim.x >> 5) + (threadIdx.x >> 5);
    if (node >= NN) return;
    int lane = threadIdx.x & 31;
    float4 qv = ((const float4*)(g_q + (size_t)node * DD))[lane];
    float m = -CUDART_INF_F, s = 0.f;
    float4 acc = make_float4(0.f, 0.f, 0.f, 0.f);
    int e0 = g_off[node], e1 = g_off[node + 1];
    for (int e = e0; e < e1; e++) {
        int src = g_csr[e];
        float4 kv = ((const float4*)(g_k + (size_t)src * DD))[lane];
        float4 vv = ((const float4*)(g_v + (size_t)src * DD))[lane];
        float p = qv.x * kv.x + qv.y * kv.y + qv.z * kv.z + qv.w * kv.w;
        p += __shfl_xor_sync(0xFFFFFFFFu, p, 1);
        p += __shfl_xor_sync(0xFFFFFFFFu, p, 2);
        float score = p * 0.25f;  // 1/sqrt(DH=16)
        float mnew = fmaxf(m, score);
        float f = __expf(m - mnew);     // 0 on first edge (m = -inf)
        float w = __expf(score - mnew);
        s = s * f + w;
        acc.x = acc.x * f + w * vv.x;
        acc.y = acc.y * f + w * vv.y;
        acc.z = acc.z * f + w * vv.z;
        acc.w = acc.w * f + w * vv.w;
        m = mnew;
    }
    float inv = (s > 0.f) ? 1.f / s : 0.f;
    float4 o = make_float4(acc.x * inv, acc.y * inv, acc.z * inv, acc.w * inv);
    ((float4*)(g_agg + (size_t)node * DD))[lane] = o;
}

// ---------------- host-side launch -----------------------------------------
static inline void run_gemm(int bias, int relu, const float* A, const float* B,
                            const float* bp, float* C, int M, int N, int K) {
    dim3 grid((N + 127) / 128, (M + 127) / 128);
    if (bias && relu)      sgemm_kernel<1, 1><<<grid, 256>>>(A, B, bp, C, M, N, K);
    else if (bias)         sgemm_kernel<1, 0><<<grid, 256>>>(A, B, bp, C, M, N, K);
    else                   sgemm_kernel<0, 0><<<grid, 256>>>(A, B, bp, C, M, N, K);
}

extern "C" void kernel_launch(void* const* d_in, const int* in_sizes, int n_in,
                              void* d_out, int out_size) {
    const float* X        = (const float*)d_in[0];
    const int*   ei       = (const int*)d_in[1];
    const float* emb_w    = (const float*)d_in[2];
    const float* emb_b    = (const float*)d_in[3];
    const float* emb_ln_g = (const float*)d_in[4];
    const float* emb_ln_b = (const float*)d_in[5];
    const float* Wq       = (const float*)d_in[6];
    const float* Wk       = (const float*)d_in[7];
    const float* Wv       = (const float*)d_in[8];
    const float* Wo       = (const float*)d_in[9];
    const float* ln_g     = (const float*)d_in[10];
    const float* ln_b     = (const float*)d_in[11];
    const float* f1_w     = (const float*)d_in[12];
    const float* f1_b     = (const float*)d_in[13];
    const float* f2_w     = (const float*)d_in[14];
    const float* f2_b     = (const float*)d_in[15];
    const float* f3_w     = (const float*)d_in[16];
    const float* f3_b     = (const float*)d_in[17];
    float* out = (float*)d_out;

    const int* src = ei;
    const int* dst = ei + EE;

    float *p_h, *p_q, *p_k, *p_v, *p_agg, *p_t, *p_t2;
    cudaGetSymbolAddress((void**)&p_h,   g_h);
    cudaGetSymbolAddress((void**)&p_q,   g_q);
    cudaGetSymbolAddress((void**)&p_k,   g_k);
    cudaGetSymbolAddress((void**)&p_v,   g_v);
    cudaGetSymbolAddress((void**)&p_agg, g_agg);
    cudaGetSymbolAddress((void**)&p_t,   g_t);
    cudaGetSymbolAddress((void**)&p_t2,  g_t2);

    // ---- CSR build (by dst) ----
    zero_deg_kernel<<<(NN + 255) / 256, 256>>>();
    count_deg_kernel<<<(EE + 255) / 256, 256>>>(dst);
    scan_kernel<<<1, 1024>>>();
    scatter_kernel<<<(EE + 255) / 256, 256>>>(src, dst);

    // ---- embedding: relu(X @ emb_w + b) -> LN -> h ----
    run_gemm(1, 1, X, emb_w, emb_b, p_t, NN, DD, DIN);
    ln_kernel<0><<<(NN + 7) / 8, 256>>>(p_t, nullptr, emb_ln_g, emb_ln_b, p_h);

    // ---- layers ----
    for (int l = 0; l < LL; l++) {
        const float* wq = Wq + (size_t)l * DD * DD;
        const float* wk = Wk + (size_t)l * DD * DD;
        const float* wv = Wv + (size_t)l * DD * DD;
        const float* wo = Wo + (size_t)l * DD * DD;
        run_gemm(0, 0, p_h, wq, nullptr, p_q, NN, DD, DD);
        run_gemm(0, 0, p_h, wk, nullptr, p_k, NN, DD, DD);
        run_gemm(0, 0, p_h, wv, nullptr, p_v, NN, DD, DD);
        attn_kernel<<<(NN + 7) / 8, 256>>>();
        run_gemm(0, 0, p_agg, wo, nullptr, p_t, NN, DD, DD);
        ln_kernel<1><<<(NN + 7) / 8, 256>>>(p_t, p_h, ln_g + l * DD, ln_b + l * DD, p_h);
    }

    // ---- MLP head ----
    run_gemm(1, 1, p_h,  f1_w, f1_b, p_t,  NN, 512, DD);
    run_gemm(1, 1, p_t,  f2_w, f2_b, p_t2, NN, 512, 512);
    run_gemm(1, 0, p_t2, f3_w, f3_b, out,  NN, NCC, 512);
}

// round 5
// speedup vs baseline: 1.0097x; 1.0086x over previous
#include <cuda_runtime.h>
#include <math.h>
#include <math_constants.h>

#define NN 50000
#define EE 640000
#define DIN 256
#define DD 128
#define HH 8
#define NCC 47
#define LL 3

// ---------------- scratch (static device allocations; no runtime alloc) ----
__device__ float g_h[NN * DD];        // node features
__device__ float g_q[NN * DD];
__device__ float g_k[NN * DD];
__device__ float g_v[NN * DD];
__device__ float g_agg[NN * DD];
__device__ float g_t[NN * 512];       // tmp: pre-LN embed [N,128], agg@Wo [N,128], ff1 [N,512]
__device__ float g_t2[NN * 512];      // ff2 [N,512]
__device__ int   g_deg[NN];
__device__ int   g_off[NN + 1];
__device__ int   g_cur[NN];
__device__ int   g_csr[EE];

// ---------------- CSR build ------------------------------------------------
__global__ void zero_deg_kernel() {
    int i = blockIdx.x * blockDim.x + threadIdx.x;
    if (i < NN) g_deg[i] = 0;
}

__global__ void count_deg_kernel(const int* __restrict__ dst) {
    int e = blockIdx.x * blockDim.x + threadIdx.x;
    if (e < EE) atomicAdd(&g_deg[dst[e]], 1);
}

// Single-block exclusive scan over g_deg -> g_off, g_cur (warp-shuffle based)
__global__ void scan_kernel() {
    __shared__ int wsum[32];
    __shared__ int carry_s;
    int t = threadIdx.x, lane = t & 31, wid = t >> 5;
    if (t == 0) carry_s = 0;
    __syncthreads();
    for (int base = 0; base < NN; base += 1024) {
        int i = base + t;
        int val = (i < NN) ? g_deg[i] : 0;
        int incl = val;
        #pragma unroll
        for (int o = 1; o < 32; o <<= 1) {
            int x = __shfl_up_sync(0xFFFFFFFFu, incl, o);
            if (lane >= o) incl += x;
        }
        if (lane == 31) wsum[wid] = incl;
        __syncthreads();
        if (wid == 0) {
            int wv = wsum[lane];
            int wincl = wv;
            #pragma unroll
            for (int o = 1; o < 32; o <<= 1) {
                int x = __shfl_up_sync(0xFFFFFFFFu, wincl, o);
                if (lane >= o) wincl += x;
            }
            wsum[lane] = wincl - wv;  // exclusive warp prefix
        }
        __syncthreads();
        int carry = carry_s;
        int excl = carry + wsum[wid] + incl - val;
        if (i < NN) { g_off[i] = excl; g_cur[i] = excl; }
        __syncthreads();
        if (t == 1023) carry_s = carry + wsum[31] + incl;
        __syncthreads();
    }
    if (threadIdx.x == 0) g_off[NN] = carry_s;
}

__global__ void scatter_kernel(const int* __restrict__ src, const int* __restrict__ dst) {
    int e = blockIdx.x * blockDim.x + threadIdx.x;
    if (e < EE) {
        int d = dst[e];
        int pos = atomicAdd(&g_cur[d], 1);
        g_csr[pos] = src[e];
    }
}

// ---------------- SGEMM: C[M,N] = A[M,K] @ B[K,N] (+bias, relu) ------------
// BM=BN=128, BK=8, 256 threads, 8x8 microtile per thread.
template <int BIAS, int RELU>
__global__ void sgemm_kernel(const float* __restrict__ A, const float* __restrict__ B,
                             const float* __restrict__ bias, float* __restrict__ C,
                             int M, int N, int K) {
    __shared__ float As[8][128];
    __shared__ float Bs[8][128];
    int tid = threadIdx.x;
    int row0 = blockIdx.y * 128, col0 = blockIdx.x * 128;
    int tx = tid & 15, ty = tid >> 4;
    int aRow = tid >> 1, aSeg = tid & 1;
    int bRow = tid >> 5, bCol4 = tid & 31;
    float acc[8][8];
    #pragma unroll
    for (int i = 0; i < 8; i++)
        #pragma unroll
        for (int j = 0; j < 8; j++) acc[i][j] = 0.f;

    const bool nVec = ((N & 127) == 0);  // full-width column tiles: vector loads safe

    for (int k0 = 0; k0 < K; k0 += 8) {
        // A tile (128 rows x 8 k), transposed store
        {
            int gr = row0 + aRow;
            float4 va = make_float4(0.f, 0.f, 0.f, 0.f);
            if (gr < M) va = *(const float4*)(A + (size_t)gr * K + k0 + aSeg * 4);
            As[aSeg * 4 + 0][aRow] = va.x;
            As[aSeg * 4 + 1][aRow] = va.y;
            As[aSeg * 4 + 2][aRow] = va.z;
            As[aSeg * 4 + 3][aRow] = va.w;
        }
        // B tile (8 k x 128 cols)
        {
            int gc = col0 + bCol4 * 4;
            const float* bp = B + (size_t)(k0 + bRow) * N + gc;
            float4 vb;
            if (nVec) {
                vb = *(const float4*)bp;
            } else {
                vb.x = (gc + 0 < N) ? bp[0] : 0.f;
                vb.y = (gc + 1 < N) ? bp[1] : 0.f;
                vb.z = (gc + 2 < N) ? bp[2] : 0.f;
                vb.w = (gc + 3 < N) ? bp[3] : 0.f;
            }
            *(float4*)&Bs[bRow][bCol4 * 4] = vb;
        }
        __syncthreads();
        #pragma unroll
        for (int kk = 0; kk < 8; kk++) {
            float a[8], b[8];
            #pragma unroll
            for (int i = 0; i < 8; i++) a[i] = As[kk][ty * 8 + i];
            #pragma unroll
            for (int j = 0; j < 8; j++) b[j] = Bs[kk][tx * 8 + j];
            #pragma unroll
            for (int i = 0; i < 8; i++)
                #pragma unroll
                for (int j = 0; j < 8; j++)
                    acc[i][j] = fmaf(a[i], b[j], acc[i][j]);
        }
        __syncthreads();
    }

    #pragma unroll
    for (int i = 0; i < 8; i++) {
        int r = row0 + ty * 8 + i;
        if (r >= M) break;
        #pragma unroll
        for (int j = 0; j < 8; j++) {
            int c = col0 + tx * 8 + j;
            if (c < N) {
                float val = acc[i][j];
                if (BIAS) val += bias[c];
                if (RELU) val = fmaxf(val, 0.f);
                C[(size_t)r * N + c] = val;
            }
        }
    }
}

// ---------------- LayerNorm over D=128 (warp per node) ---------------------
template <int RESID>
__global__ void ln_kernel(const float* __restrict__ X, const float* __restrict__ R,
                          const float* __restrict__ g, const float* __restrict__ b,
                          float* __restrict__ out) {
    int node = blockIdx.x * (blockDim.x >> 5) + (threadIdx.x >> 5);
    if (node >= NN) return;
    int lane = threadIdx.x & 31;
    float4 x = ((const float4*)(X + (size_t)node * DD))[lane];
    if (RESID) {
        float4 r = ((const float4*)(R + (size_t)node * DD))[lane];
        x.x += r.x; x.y += r.y; x.z += r.z; x.w += r.w;
    }
    float s = x.x + x.y + x.z + x.w;
    #pragma unroll
    for (int o = 16; o; o >>= 1) s += __shfl_xor_sync(0xFFFFFFFFu, s, o);
    float mu = s * (1.f / 128.f);
    float dx = x.x - mu, dy = x.y - mu, dz = x.z - mu, dw = x.w - mu;
    float v = dx * dx + dy * dy + dz * dz + dw * dw;
    #pragma unroll
    for (int o = 16; o; o >>= 1) v += __shfl_xor_sync(0xFFFFFFFFu, v, o);
    float rstd = rsqrtf(v * (1.f / 128.f) + 1e-5f);
    float4 gg = ((const float4*)g)[lane];
    float4 bb = ((const float4*)b)[lane];
    float4 o4;
    o4.x = dx * rstd * gg.x + bb.x;
    o4.y = dy * rstd * gg.y + bb.y;
    o4.z = dz * rstd * gg.z + bb.z;
    o4.w = dw * rstd * gg.w + bb.w;
    ((float4*)(out + (size_t)node * DD))[lane] = o4;
}

// ---------------- attention + aggregation (warp per dst node) --------------
// lane covers dims [4*lane, 4*lane+4); head = lane/4 (DH=16 -> 4 lanes/head).
__global__ void attn_kernel() {
    int node = blockIdx.x * (blockDim.x >> 5) + (threadIdx.x >> 5);
    if (node >= NN) return;
    int lane = threadIdx.x & 31;
    float4 qv = ((const float4*)(g_q + (size_t)node * DD))[lane];
    float m = -CUDART_INF_F, s = 0.f;
    float4 acc = make_float4(0.f, 0.f, 0.f, 0.f);
    int e0 = g_off[node], e1 = g_off[node + 1];
    for (int e = e0; e < e1; e++) {
        int src = g_csr[e];
        float4 kv = ((const float4*)(g_k + (size_t)src * DD))[lane];
        float4 vv = ((const float4*)(g_v + (size_t)src * DD))[lane];
        float p = qv.x * kv.x + qv.y * kv.y + qv.z * kv.z + qv.w * kv.w;
        p += __shfl_xor_sync(0xFFFFFFFFu, p, 1);
        p += __shfl_xor_sync(0xFFFFFFFFu, p, 2);
        float score = p * 0.25f;  // 1/sqrt(DH=16)
        float mnew = fmaxf(m, score);
        float f = __expf(m - mnew);     // 0 on first edge (m = -inf)
        float w = __expf(score - mnew);
        s = s * f + w;
        acc.x = acc.x * f + w * vv.x;
        acc.y = acc.y * f + w * vv.y;
        acc.z = acc.z * f + w * vv.z;
        acc.w = acc.w * f + w * vv.w;
        m = mnew;
    }
    float inv = (s > 0.f) ? 1.f / s : 0.f;
    float4 o = make_float4(acc.x * inv, acc.y * inv, acc.z * inv, acc.w * inv);
    ((float4*)(g_agg + (size_t)node * DD))[lane] = o;
}

// ---------------- host-side launch -----------------------------------------
static inline void run_gemm(int bias, int relu, const float* A, const float* B,
                            const float* bp, float* C, int M, int N, int K) {
    dim3 grid((N + 127) / 128, (M + 127) / 128);
    if (bias && relu)      sgemm_kernel<1, 1><<<grid, 256>>>(A, B, bp, C, M, N, K);
    else if (bias)         sgemm_kernel<1, 0><<<grid, 256>>>(A, B, bp, C, M, N, K);
    else                   sgemm_kernel<0, 0><<<grid, 256>>>(A, B, bp, C, M, N, K);
}

extern "C" void kernel_launch(void* const* d_in, const int* in_sizes, int n_in,
                              void* d_out, int out_size) {
    const float* X        = (const float*)d_in[0];
    const int*   ei       = (const int*)d_in[1];
    const float* emb_w    = (const float*)d_in[2];
    const float* emb_b    = (const float*)d_in[3];
    const float* emb_ln_g = (const float*)d_in[4];
    const float* emb_ln_b = (const float*)d_in[5];
    const float* Wq       = (const float*)d_in[6];
    const float* Wk       = (const float*)d_in[7];
    const float* Wv       = (const float*)d_in[8];
    const float* Wo       = (const float*)d_in[9];
    const float* ln_g     = (const float*)d_in[10];
    const float* ln_b     = (const float*)d_in[11];
    const float* f1_w     = (const float*)d_in[12];
    const float* f1_b     = (const float*)d_in[13];
    const float* f2_w     = (const float*)d_in[14];
    const float* f2_b     = (const float*)d_in[15];
    const float* f3_w     = (const float*)d_in[16];
    const float* f3_b     = (const float*)d_in[17];
    float* out = (float*)d_out;

    const int* src = ei;
    const int* dst = ei + EE;

    float *p_h, *p_q, *p_k, *p_v, *p_agg, *p_t, *p_t2;
    cudaGetSymbolAddress((void**)&p_h,   g_h);
    cudaGetSymbolAddress((void**)&p_q,   g_q);
    cudaGetSymbolAddress((void**)&p_k,   g_k);
    cudaGetSymbolAddress((void**)&p_v,   g_v);
    cudaGetSymbolAddress((void**)&p_agg, g_agg);
    cudaGetSymbolAddress((void**)&p_t,   g_t);
    cudaGetSymbolAddress((void**)&p_t2,  g_t2);

    // ---- CSR build (by dst) ----
    zero_deg_kernel<<<(NN + 255) / 256, 256>>>();
    count_deg_kernel<<<(EE + 255) / 256, 256>>>(dst);
    scan_kernel<<<1, 1024>>>();
    scatter_kernel<<<(EE + 255) / 256, 256>>>(src, dst);

    // ---- embedding: relu(X @ emb_w + b) -> LN -> h ----
    run_gemm(1, 1, X, emb_w, emb_b, p_t, NN, DD, DIN);
    ln_kernel<0><<<(NN + 7) / 8, 256>>>(p_t, nullptr, emb_ln_g, emb_ln_b, p_h);

    // ---- layers ----
    for (int l = 0; l < LL; l++) {
        const float* wq = Wq + (size_t)l * DD * DD;
        const float* wk = Wk + (size_t)l * DD * DD;
        const float* wv = Wv + (size_t)l * DD * DD;
        const float* wo = Wo + (size_t)l * DD * DD;
        run_gemm(0, 0, p_h, wq, nullptr, p_q, NN, DD, DD);
        run_gemm(0, 0, p_h, wk, nullptr, p_k, NN, DD, DD);
        run_gemm(0, 0, p_h, wv, nullptr, p_v, NN, DD, DD);
        attn_kernel<<<(NN + 7) / 8, 256>>>();
        run_gemm(0, 0, p_agg, wo, nullptr, p_t, NN, DD, DD);
        ln_kernel<1><<<(NN + 7) / 8, 256>>>(p_t, p_h, ln_g + l * DD, ln_b + l * DD, p_h);
    }

    // ---- MLP head ----
    run_gemm(1, 1, p_h,  f1_w, f1_b, p_t,  NN, 512, DD);
    run_gemm(1, 1, p_t,  f2_w, f2_b, p_t2, NN, 512, 512);
    run_gemm(1, 0, p_t2, f3_w, f3_b, out,  NN, NCC, 512);
}

// round 7
// speedup vs baseline: 2.0180x; 1.9985x over previous
#include <cuda_runtime.h>
#include <math.h>
#include <math_constants.h>

#define NN 50000
#define EE 640000
#define DIN 256
#define DD 128
#define HH 8
#define NCC 47
#define LL 3

// ---------------- scratch (static device allocations; no runtime alloc) ----
__device__ float g_h[NN * DD];
__device__ float g_q[NN * DD];
__device__ float g_k[NN * DD];
__device__ float g_v[NN * DD];
__device__ float g_agg[NN * DD];
__device__ float g_t[NN * 512];
__device__ float g_t2[NN * 512];
__device__ int   g_deg[NN];
__device__ int   g_off[NN + 1];
__device__ int   g_cur[NN];
__device__ int   g_csr[EE];

// ---------------- CSR build ------------------------------------------------
__global__ void zero_deg_kernel() {
    int i = blockIdx.x * blockDim.x + threadIdx.x;
    if (i < NN) g_deg[i] = 0;
}

__global__ void count_deg_kernel(const int* __restrict__ dst) {
    int e = blockIdx.x * blockDim.x + threadIdx.x;
    if (e < EE) atomicAdd(&g_deg[dst[e]], 1);
}

__global__ void scan_kernel() {
    __shared__ int wsum[32];
    __shared__ int carry_s;
    int t = threadIdx.x, lane = t & 31, wid = t >> 5;
    if (t == 0) carry_s = 0;
    __syncthreads();
    for (int base = 0; base < NN; base += 1024) {
        int i = base + t;
        int val = (i < NN) ? g_deg[i] : 0;
        int incl = val;
        #pragma unroll
        for (int o = 1; o < 32; o <<= 1) {
            int x = __shfl_up_sync(0xFFFFFFFFu, incl, o);
            if (lane >= o) incl += x;
        }
        if (lane == 31) wsum[wid] = incl;
        __syncthreads();
        if (wid == 0) {
            int wv = wsum[lane];
            int wincl = wv;
            #pragma unroll
            for (int o = 1; o < 32; o <<= 1) {
                int x = __shfl_up_sync(0xFFFFFFFFu, wincl, o);
                if (lane >= o) wincl += x;
            }
            wsum[lane] = wincl - wv;
        }
        __syncthreads();
        int carry = carry_s;
        int excl = carry + wsum[wid] + incl - val;
        if (i < NN) { g_off[i] = excl; g_cur[i] = excl; }
        __syncthreads();
        if (t == 1023) carry_s = carry + wsum[31] + incl;
        __syncthreads();
    }
    if (threadIdx.x == 0) g_off[NN] = carry_s;
}

__global__ void scatter_kernel(const int* __restrict__ src, const int* __restrict__ dst) {
    int e = blockIdx.x * blockDim.x + threadIdx.x;
    if (e < EE) {
        int d = dst[e];
        int pos = atomicAdd(&g_cur[d], 1);
        g_csr[pos] = src[e];
    }
}

// ---------------- TF32 tensor-core GEMM ------------------------------------
// C[M,N] = A[M,K] @ B[K,N] (+bias, relu).  BM=BN=128, BK=16, 256 threads.
// 8 warps in 4(M)x2(N) layout, each warp computes 32x64 via m16n8k8 tf32 mma.
__device__ __forceinline__ unsigned f2tf(float f) {
    unsigned u;
    asm("cvt.rna.tf32.f32 %0, %1;" : "=r"(u) : "f"(f));
    return u;
}

template <int BIAS, int RELU>
__global__ void __launch_bounds__(256)
tf32gemm_kernel(const float* __restrict__ A, const float* __restrict__ B,
                const float* __restrict__ bias, float* __restrict__ C,
                int M, int N, int K) {
    __shared__ unsigned As[16][136];   // As[k][m], pad 8 -> conflict-free frag loads
    __shared__ unsigned Bs[16][136];   // Bs[k][n]
    int tid = threadIdx.x, lane = tid & 31, wid = tid >> 5;
    int row0 = blockIdx.y * 128, col0 = blockIdx.x * 128;
    int wm = (wid & 3) * 32, wn = (wid >> 2) * 64;
    int g = lane >> 2, c = lane & 3;

    int aRow = tid >> 1, aSeg = tid & 1;    // A: 1 row, 8 k-floats per thread
    int bRow = tid >> 5;                    // B: rows bRow, bRow+8; 4 n-floats/lane

    float acc[2][8][4];
    #pragma unroll
    for (int i = 0; i < 2; i++)
        #pragma unroll
        for (int j = 0; j < 8; j++)
            #pragma unroll
            for (int r = 0; r < 4; r++) acc[i][j][r] = 0.f;

    const bool nVec = ((N & 127) == 0);    // full-width tiles: vector B loads safe
    const bool nEven = ((N & 1) == 0);     // even N: float2 C stores 8B-aligned

    for (int k0 = 0; k0 < K; k0 += 16) {
        // A tile: 128 rows x 16 k, transposed into As[k][m] as tf32
        {
            int gr = row0 + aRow;
            float4 v0 = make_float4(0.f, 0.f, 0.f, 0.f), v1 = v0;
            if (gr < M) {
                const float* ap = A + (size_t)gr * K + k0 + aSeg * 8;
                v0 = ((const float4*)ap)[0];
                v1 = ((const float4*)ap)[1];
            }
            int kb = aSeg * 8;
            As[kb + 0][aRow] = f2tf(v0.x);
            As[kb + 1][aRow] = f2tf(v0.y);
            As[kb + 2][aRow] = f2tf(v0.z);
            As[kb + 3][aRow] = f2tf(v0.w);
            As[kb + 4][aRow] = f2tf(v1.x);
            As[kb + 5][aRow] = f2tf(v1.y);
            As[kb + 6][aRow] = f2tf(v1.z);
            As[kb + 7][aRow] = f2tf(v1.w);
        }
        // B tile: 16 k x 128 n
        #pragma unroll
        for (int hh = 0; hh < 2; hh++) {
            int kr = bRow + hh * 8;
            int gc = col0 + lane * 4;
            const float* bp = B + (size_t)(k0 + kr) * N + gc;
            float4 vb;
            if (nVec) {
                vb = *(const float4*)bp;
            } else {
                vb.x = (gc + 0 < N) ? bp[0] : 0.f;
                vb.y = (gc + 1 < N) ? bp[1] : 0.f;
                vb.z = (gc + 2 < N) ? bp[2] : 0.f;
                vb.w = (gc + 3 < N) ? bp[3] : 0.f;
            }
            Bs[kr][lane * 4 + 0] = f2tf(vb.x);
            Bs[kr][lane * 4 + 1] = f2tf(vb.y);
            Bs[kr][lane * 4 + 2] = f2tf(vb.z);
            Bs[kr][lane * 4 + 3] = f2tf(vb.w);
        }
        __syncthreads();

        #pragma unroll
        for (int ks = 0; ks < 2; ks++) {
            int kb = ks * 8;
            unsigned a[2][4];
            #pragma unroll
            for (int i = 0; i < 2; i++) {
                int m = wm + 16 * i + g;
                a[i][0] = As[kb + c][m];
                a[i][1] = As[kb + c][m + 8];
                a[i][2] = As[kb + c + 4][m];
                a[i][3] = As[kb + c + 4][m + 8];
            }
            #pragma unroll
            for (int j = 0; j < 8; j++) {
                unsigned b0 = Bs[kb + c][wn + 8 * j + g];
                unsigned b1 = Bs[kb + c + 4][wn + 8 * j + g];
                #pragma unroll
                for (int i = 0; i < 2; i++) {
                    asm volatile(
                        "mma.sync.aligned.m16n8k8.row.col.f32.tf32.tf32.f32 "
                        "{%0,%1,%2,%3}, {%4,%5,%6,%7}, {%8,%9}, {%0,%1,%2,%3};"
                        : "+f"(acc[i][j][0]), "+f"(acc[i][j][1]),
                          "+f"(acc[i][j][2]), "+f"(acc[i][j][3])
                        : "r"(a[i][0]), "r"(a[i][1]), "r"(a[i][2]), "r"(a[i][3]),
                          "r"(b0), "r"(b1));
                }
            }
        }
        __syncthreads();
    }

    // epilogue
    #pragma unroll
    for (int i = 0; i < 2; i++) {
        int r = row0 + wm + 16 * i + g;
        #pragma unroll
        for (int j = 0; j < 8; j++) {
            int cc = col0 + wn + 8 * j + 2 * c;
            #pragma unroll
            for (int hh = 0; hh < 2; hh++) {
                int rr = r + hh * 8;
                if (rr < M) {
                    float v0 = acc[i][j][hh * 2 + 0];
                    float v1 = acc[i][j][hh * 2 + 1];
                    float* cp = C + (size_t)rr * N + cc;
                    if (nEven) {
                        if (cc + 1 < N) {
                            if (BIAS) { v0 += bias[cc]; v1 += bias[cc + 1]; }
                            if (RELU) { v0 = fmaxf(v0, 0.f); v1 = fmaxf(v1, 0.f); }
                            *(float2*)cp = make_float2(v0, v1);
                        } else if (cc < N) {
                            if (BIAS) v0 += bias[cc];
                            if (RELU) v0 = fmaxf(v0, 0.f);
                            cp[0] = v0;
                        }
                    } else {
                        // odd N (e.g. 47): scalar stores, 4B-aligned only
                        if (cc < N) {
                            if (BIAS) v0 += bias[cc];
                            if (RELU) v0 = fmaxf(v0, 0.f);
                            cp[0] = v0;
                        }
                        if (cc + 1 < N) {
                            if (BIAS) v1 += bias[cc + 1];
                            if (RELU) v1 = fmaxf(v1, 0.f);
                            cp[1] = v1;
                        }
                    }
                }
            }
        }
    }
}

// ---------------- LayerNorm over D=128 (warp per node) ---------------------
template <int RESID>
__global__ void ln_kernel(const float* __restrict__ X, const float* __restrict__ R,
                          const float* __restrict__ g, const float* __restrict__ b,
                          float* __restrict__ out) {
    int node = blockIdx.x * (blockDim.x >> 5) + (threadIdx.x >> 5);
    if (node >= NN) return;
    int lane = threadIdx.x & 31;
    float4 x = ((const float4*)(X + (size_t)node * DD))[lane];
    if (RESID) {
        float4 r = ((const float4*)(R + (size_t)node * DD))[lane];
        x.x += r.x; x.y += r.y; x.z += r.z; x.w += r.w;
    }
    float s = x.x + x.y + x.z + x.w;
    #pragma unroll
    for (int o = 16; o; o >>= 1) s += __shfl_xor_sync(0xFFFFFFFFu, s, o);
    float mu = s * (1.f / 128.f);
    float dx = x.x - mu, dy = x.y - mu, dz = x.z - mu, dw = x.w - mu;
    float v = dx * dx + dy * dy + dz * dz + dw * dw;
    #pragma unroll
    for (int o = 16; o; o >>= 1) v += __shfl_xor_sync(0xFFFFFFFFu, v, o);
    float rstd = rsqrtf(v * (1.f / 128.f) + 1e-5f);
    float4 gg = ((const float4*)g)[lane];
    float4 bb = ((const float4*)b)[lane];
    float4 o4;
    o4.x = dx * rstd * gg.x + bb.x;
    o4.y = dy * rstd * gg.y + bb.y;
    o4.z = dz * rstd * gg.z + bb.z;
    o4.w = dw * rstd * gg.w + bb.w;
    ((float4*)(out + (size_t)node * DD))[lane] = o4;
}

// ---------------- attention + aggregation (warp per dst node) --------------
__global__ void attn_kernel() {
    int node = blockIdx.x * (blockDim.x >> 5) + (threadIdx.x >> 5);
    if (node >= NN) return;
    int lane = threadIdx.x & 31;
    float4 qv = ((const float4*)(g_q + (size_t)node * DD))[lane];
    float m = -CUDART_INF_F, s = 0.f;
    float4 acc = make_float4(0.f, 0.f, 0.f, 0.f);
    int e0 = g_off[node], e1 = g_off[node + 1];
    for (int e = e0; e < e1; e++) {
        int src = g_csr[e];
        float4 kv = ((const float4*)(g_k + (size_t)src * DD))[lane];
        float4 vv = ((const float4*)(g_v + (size_t)src * DD))[lane];
        float p = qv.x * kv.x + qv.y * kv.y + qv.z * kv.z + qv.w * kv.w;
        p += __shfl_xor_sync(0xFFFFFFFFu, p, 1);
        p += __shfl_xor_sync(0xFFFFFFFFu, p, 2);
        float score = p * 0.25f;
        float mnew = fmaxf(m, score);
        float f = __expf(m - mnew);
        float w = __expf(score - mnew);
        s = s * f + w;
        acc.x = acc.x * f + w * vv.x;
        acc.y = acc.y * f + w * vv.y;
        acc.z = acc.z * f + w * vv.z;
        acc.w = acc.w * f + w * vv.w;
        m = mnew;
    }
    float inv = (s > 0.f) ? 1.f / s : 0.f;
    float4 o = make_float4(acc.x * inv, acc.y * inv, acc.z * inv, acc.w * inv);
    ((float4*)(g_agg + (size_t)node * DD))[lane] = o;
}

// ---------------- host-side launch -----------------------------------------
static inline void run_gemm(int bias, int relu, const float* A, const float* B,
                            const float* bp, float* C, int M, int N, int K) {
    dim3 grid((N + 127) / 128, (M + 127) / 128);
    if (bias && relu)      tf32gemm_kernel<1, 1><<<grid, 256>>>(A, B, bp, C, M, N, K);
    else if (bias)         tf32gemm_kernel<1, 0><<<grid, 256>>>(A, B, bp, C, M, N, K);
    else                   tf32gemm_kernel<0, 0><<<grid, 256>>>(A, B, bp, C, M, N, K);
}

extern "C" void kernel_launch(void* const* d_in, const int* in_sizes, int n_in,
                              void* d_out, int out_size) {
    const float* X        = (const float*)d_in[0];
    const int*   ei       = (const int*)d_in[1];
    const float* emb_w    = (const float*)d_in[2];
    const float* emb_b    = (const float*)d_in[3];
    const float* emb_ln_g = (const float*)d_in[4];
    const float* emb_ln_b = (const float*)d_in[5];
    const float* Wq       = (const float*)d_in[6];
    const float* Wk       = (const float*)d_in[7];
    const float* Wv       = (const float*)d_in[8];
    const float* Wo       = (const float*)d_in[9];
    const float* ln_g     = (const float*)d_in[10];
    const float* ln_b     = (const float*)d_in[11];
    const float* f1_w     = (const float*)d_in[12];
    const float* f1_b     = (const float*)d_in[13];
    const float* f2_w     = (const float*)d_in[14];
    const float* f2_b     = (const float*)d_in[15];
    const float* f3_w     = (const float*)d_in[16];
    const float* f3_b     = (const float*)d_in[17];
    float* out = (float*)d_out;

    const int* src = ei;
    const int* dst = ei + EE;

    float *p_h, *p_q, *p_k, *p_v, *p_agg, *p_t, *p_t2;
    cudaGetSymbolAddress((void**)&p_h,   g_h);
    cudaGetSymbolAddress((void**)&p_q,   g_q);
    cudaGetSymbolAddress((void**)&p_k,   g_k);
    cudaGetSymbolAddress((void**)&p_v,   g_v);
    cudaGetSymbolAddress((void**)&p_agg, g_agg);
    cudaGetSymbolAddress((void**)&p_t,   g_t);
    cudaGetSymbolAddress((void**)&p_t2,  g_t2);

    // ---- CSR build (by dst) ----
    zero_deg_kernel<<<(NN + 255) / 256, 256>>>();
    count_deg_kernel<<<(EE + 255) / 256, 256>>>(dst);
    scan_kernel<<<1, 1024>>>();
    scatter_kernel<<<(EE + 255) / 256, 256>>>(src, dst);

    // ---- embedding: relu(X @ emb_w + b) -> LN -> h ----
    run_gemm(1, 1, X, emb_w, emb_b, p_t, NN, DD, DIN);
    ln_kernel<0><<<(NN + 7) / 8, 256>>>(p_t, nullptr, emb_ln_g, emb_ln_b, p_h);

    // ---- layers ----
    for (int l = 0; l < LL; l++) {
        const float* wq = Wq + (size_t)l * DD * DD;
        const float* wk = Wk + (size_t)l * DD * DD;
        const float* wv = Wv + (size_t)l * DD * DD;
        const float* wo = Wo + (size_t)l * DD * DD;
        run_gemm(0, 0, p_h, wq, nullptr, p_q, NN, DD, DD);
        run_gemm(0, 0, p_h, wk, nullptr, p_k, NN, DD, DD);
        run_gemm(0, 0, p_h, wv, nullptr, p_v, NN, DD, DD);
        attn_kernel<<<(NN + 7) / 8, 256>>>();
        run_gemm(0, 0, p_agg, wo, nullptr, p_t, NN, DD, DD);
        ln_kernel<1><<<(NN + 7) / 8, 256>>>(p_t, p_h, ln_g + l * DD, ln_b + l * DD, p_h);
    }

    // ---- MLP head ----
    run_gemm(1, 1, p_h,  f1_w, f1_b, p_t,  NN, 512, DD);
    run_gemm(1, 1, p_t,  f2_w, f2_b, p_t2, NN, 512, 512);
    run_gemm(1, 0, p_t2, f3_w, f3_b, out,  NN, NCC, 512);
}

// round 8
// speedup vs baseline: 2.5423x; 1.2598x over previous
#include <cuda_runtime.h>
#include <math.h>
#include <math_constants.h>

#define NN 50000
#define EE 640000
#define DIN 256
#define DD 128
#define HH 8
#define NCC 47
#define LL 3

// ---------------- scratch (static device allocations; no runtime alloc) ----
__device__ float g_h[NN * DD];
__device__ float g_q[NN * DD];
__device__ float g_k[NN * DD];
__device__ float g_v[NN * DD];
__device__ float g_agg[NN * DD];
__device__ float g_t[NN * 512];
__device__ float g_t2[NN * 512];
__device__ int   g_deg[NN];
__device__ int   g_off[NN + 1];
__device__ int   g_cur[NN];
__device__ int   g_csr[EE];

// ---------------- CSR build ------------------------------------------------
__global__ void zero_deg_kernel() {
    int i = blockIdx.x * blockDim.x + threadIdx.x;
    if (i < NN) g_deg[i] = 0;
}

__global__ void count_deg_kernel(const int* __restrict__ dst) {
    int e = blockIdx.x * blockDim.x + threadIdx.x;
    if (e < EE) atomicAdd(&g_deg[dst[e]], 1);
}

__global__ void scan_kernel() {
    __shared__ int wsum[32];
    __shared__ int carry_s;
    int t = threadIdx.x, lane = t & 31, wid = t >> 5;
    if (t == 0) carry_s = 0;
    __syncthreads();
    for (int base = 0; base < NN; base += 1024) {
        int i = base + t;
        int val = (i < NN) ? g_deg[i] : 0;
        int incl = val;
        #pragma unroll
        for (int o = 1; o < 32; o <<= 1) {
            int x = __shfl_up_sync(0xFFFFFFFFu, incl, o);
            if (lane >= o) incl += x;
        }
        if (lane == 31) wsum[wid] = incl;
        __syncthreads();
        if (wid == 0) {
            int wv = wsum[lane];
            int wincl = wv;
            #pragma unroll
            for (int o = 1; o < 32; o <<= 1) {
                int x = __shfl_up_sync(0xFFFFFFFFu, wincl, o);
                if (lane >= o) wincl += x;
            }
            wsum[lane] = wincl - wv;
        }
        __syncthreads();
        int carry = carry_s;
        int excl = carry + wsum[wid] + incl - val;
        if (i < NN) { g_off[i] = excl; g_cur[i] = excl; }
        __syncthreads();
        if (t == 1023) carry_s = carry + wsum[31] + incl;
        __syncthreads();
    }
    if (threadIdx.x == 0) g_off[NN] = carry_s;
}

__global__ void scatter_kernel(const int* __restrict__ src, const int* __restrict__ dst) {
    int e = blockIdx.x * blockDim.x + threadIdx.x;
    if (e < EE) {
        int d = dst[e];
        int pos = atomicAdd(&g_cur[d], 1);
        g_csr[pos] = src[e];
    }
}

// ---------------- TF32 tensor-core GEMM (double-buffered) ------------------
// C[M,N] = A[M,K] @ B[K,N] (+bias, relu).  BM=BN=128, BK=16, 256 threads.
// 8 warps in 4(M)x2(N) layout, 32x64 warp tile via m16n8k8 tf32 mma.
// Two-stage smem pipeline: prefetch next K-tile globals into registers while
// computing, store to alternate buffer, ONE barrier per K-step.
__device__ __forceinline__ unsigned f2tf(float f) {
    unsigned u;
    asm("cvt.rna.tf32.f32 %0, %1;" : "=r"(u) : "f"(f));
    return u;
}

#define GEMM_SMEM_BYTES (2 * 2 * 16 * 136 * 4)

template <int BIAS, int RELU>
__global__ void __launch_bounds__(256)
tf32gemm_kernel(const float* __restrict__ A, const float* __restrict__ B,
                const float* __restrict__ bias, float* __restrict__ C,
                int M, int N, int K) {
    extern __shared__ unsigned sm[];
    unsigned (*As)[16][136] = (unsigned (*)[16][136])sm;              // [2][16][136]
    unsigned (*Bs)[16][136] = (unsigned (*)[16][136])(sm + 2 * 16 * 136);

    int tid = threadIdx.x, lane = tid & 31, wid = tid >> 5;
    int row0 = blockIdx.y * 128, col0 = blockIdx.x * 128;
    int wm = (wid & 3) * 32, wn = (wid >> 2) * 64;
    int g = lane >> 2, c = lane & 3;

    int aRow = tid >> 1, aSeg = tid & 1;    // A: 1 row, 8 k-floats per thread
    int bRow = tid >> 5;                    // B: rows bRow, bRow+8; 4 n-floats/lane
    int gr = row0 + aRow;
    int gc = col0 + lane * 4;

    const bool nVec = ((N & 127) == 0);
    const bool nEven = ((N & 1) == 0);

    float acc[2][8][4];
    #pragma unroll
    for (int i = 0; i < 2; i++)
        #pragma unroll
        for (int j = 0; j < 8; j++)
            #pragma unroll
            for (int r = 0; r < 4; r++) acc[i][j][r] = 0.f;

    float4 pa0, pa1, pb0, pb1;

    // ---- global fetch of one K-tile into registers ----
    auto fetch = [&](int k0) {
        pa0 = make_float4(0.f, 0.f, 0.f, 0.f); pa1 = pa0;
        if (gr < M) {
            const float* ap = A + (size_t)gr * K + k0 + aSeg * 8;
            pa0 = ((const float4*)ap)[0];
            pa1 = ((const float4*)ap)[1];
        }
        const float* bp0 = B + (size_t)(k0 + bRow) * N + gc;
        const float* bp1 = B + (size_t)(k0 + bRow + 8) * N + gc;
        if (nVec) {
            pb0 = *(const float4*)bp0;
            pb1 = *(const float4*)bp1;
        } else {
            pb0.x = (gc + 0 < N) ? bp0[0] : 0.f;
            pb0.y = (gc + 1 < N) ? bp0[1] : 0.f;
            pb0.z = (gc + 2 < N) ? bp0[2] : 0.f;
            pb0.w = (gc + 3 < N) ? bp0[3] : 0.f;
            pb1.x = (gc + 0 < N) ? bp1[0] : 0.f;
            pb1.y = (gc + 1 < N) ? bp1[1] : 0.f;
            pb1.z = (gc + 2 < N) ? bp1[2] : 0.f;
            pb1.w = (gc + 3 < N) ? bp1[3] : 0.f;
        }
    };
    // ---- store registers to smem stage s (tf32-converted) ----
    auto stage = [&](int s) {
        int kb = aSeg * 8;
        As[s][kb + 0][aRow] = f2tf(pa0.x);
        As[s][kb + 1][aRow] = f2tf(pa0.y);
        As[s][kb + 2][aRow] = f2tf(pa0.z);
        As[s][kb + 3][aRow] = f2tf(pa0.w);
        As[s][kb + 4][aRow] = f2tf(pa1.x);
        As[s][kb + 5][aRow] = f2tf(pa1.y);
        As[s][kb + 6][aRow] = f2tf(pa1.z);
        As[s][kb + 7][aRow] = f2tf(pa1.w);
        Bs[s][bRow][lane * 4 + 0] = f2tf(pb0.x);
        Bs[s][bRow][lane * 4 + 1] = f2tf(pb0.y);
        Bs[s][bRow][lane * 4 + 2] = f2tf(pb0.z);
        Bs[s][bRow][lane * 4 + 3] = f2tf(pb0.w);
        Bs[s][bRow + 8][lane * 4 + 0] = f2tf(pb1.x);
        Bs[s][bRow + 8][lane * 4 + 1] = f2tf(pb1.y);
        Bs[s][bRow + 8][lane * 4 + 2] = f2tf(pb1.z);
        Bs[s][bRow + 8][lane * 4 + 3] = f2tf(pb1.w);
    };

    fetch(0);
    stage(0);
    __syncthreads();

    int s = 0;
    for (int k0 = 0; k0 < K; k0 += 16) {
        bool hasNext = (k0 + 16) < K;
        if (hasNext) fetch(k0 + 16);   // LDG overlaps the MMAs below

        #pragma unroll
        for (int ks = 0; ks < 2; ks++) {
            int kb = ks * 8;
            unsigned a[2][4];
            #pragma unroll
            for (int i = 0; i < 2; i++) {
                int m = wm + 16 * i + g;
                a[i][0] = As[s][kb + c][m];
                a[i][1] = As[s][kb + c][m + 8];
                a[i][2] = As[s][kb + c + 4][m];
                a[i][3] = As[s][kb + c + 4][m + 8];
            }
            #pragma unroll
            for (int j = 0; j < 8; j++) {
                unsigned b0 = Bs[s][kb + c][wn + 8 * j + g];
                unsigned b1 = Bs[s][kb + c + 4][wn + 8 * j + g];
                #pragma unroll
                for (int i = 0; i < 2; i++) {
                    asm volatile(
                        "mma.sync.aligned.m16n8k8.row.col.f32.tf32.tf32.f32 "
                        "{%0,%1,%2,%3}, {%4,%5,%6,%7}, {%8,%9}, {%0,%1,%2,%3};"
                        : "+f"(acc[i][j][0]), "+f"(acc[i][j][1]),
                          "+f"(acc[i][j][2]), "+f"(acc[i][j][3])
                        : "r"(a[i][0]), "r"(a[i][1]), "r"(a[i][2]), "r"(a[i][3]),
                          "r"(b0), "r"(b1));
                }
            }
        }

        if (hasNext) {
            stage(s ^ 1);
            __syncthreads();
            s ^= 1;
        }
    }

    // epilogue
    #pragma unroll
    for (int i = 0; i < 2; i++) {
        int r = row0 + wm + 16 * i + g;
        #pragma unroll
        for (int j = 0; j < 8; j++) {
            int cc = col0 + wn + 8 * j + 2 * c;
            #pragma unroll
            for (int hh = 0; hh < 2; hh++) {
                int rr = r + hh * 8;
                if (rr < M) {
                    float v0 = acc[i][j][hh * 2 + 0];
                    float v1 = acc[i][j][hh * 2 + 1];
                    float* cp = C + (size_t)rr * N + cc;
                    if (nEven) {
                        if (cc + 1 < N) {
                            if (BIAS) { v0 += bias[cc]; v1 += bias[cc + 1]; }
                            if (RELU) { v0 = fmaxf(v0, 0.f); v1 = fmaxf(v1, 0.f); }
                            *(float2*)cp = make_float2(v0, v1);
                        } else if (cc < N) {
                            if (BIAS) v0 += bias[cc];
                            if (RELU) v0 = fmaxf(v0, 0.f);
                            cp[0] = v0;
                        }
                    } else {
                        if (cc < N) {
                            if (BIAS) v0 += bias[cc];
                            if (RELU) v0 = fmaxf(v0, 0.f);
                            cp[0] = v0;
                        }
                        if (cc + 1 < N) {
                            if (BIAS) v1 += bias[cc + 1];
                            if (RELU) v1 = fmaxf(v1, 0.f);
                            cp[1] = v1;
                        }
                    }
                }
            }
        }
    }
}

// ---------------- LayerNorm over D=128 (warp per node) ---------------------
template <int RESID>
__global__ void ln_kernel(const float* __restrict__ X, const float* __restrict__ R,
                          const float* __restrict__ g, const float* __restrict__ b,
                          float* __restrict__ out) {
    int node = blockIdx.x * (blockDim.x >> 5) + (threadIdx.x >> 5);
    if (node >= NN) return;
    int lane = threadIdx.x & 31;
    float4 x = ((const float4*)(X + (size_t)node * DD))[lane];
    if (RESID) {
        float4 r = ((const float4*)(R + (size_t)node * DD))[lane];
        x.x += r.x; x.y += r.y; x.z += r.z; x.w += r.w;
    }
    float s = x.x + x.y + x.z + x.w;
    #pragma unroll
    for (int o = 16; o; o >>= 1) s += __shfl_xor_sync(0xFFFFFFFFu, s, o);
    float mu = s * (1.f / 128.f);
    float dx = x.x - mu, dy = x.y - mu, dz = x.z - mu, dw = x.w - mu;
    float v = dx * dx + dy * dy + dz * dz + dw * dw;
    #pragma unroll
    for (int o = 16; o; o >>= 1) v += __shfl_xor_sync(0xFFFFFFFFu, v, o);
    float rstd = rsqrtf(v * (1.f / 128.f) + 1e-5f);
    float4 gg = ((const float4*)g)[lane];
    float4 bb = ((const float4*)b)[lane];
    float4 o4;
    o4.x = dx * rstd * gg.x + bb.x;
    o4.y = dy * rstd * gg.y + bb.y;
    o4.z = dz * rstd * gg.z + bb.z;
    o4.w = dw * rstd * gg.w + bb.w;
    ((float4*)(out + (size_t)node * DD))[lane] = o4;
}

// ---------------- attention + aggregation (warp per dst node) --------------
// No max-subtraction needed: h is LayerNormed and W ~ 1/sqrt(D), so scores
// are O(10) and exp() cannot overflow fp32. Softmax value is identical.
// 2-edge unroll puts 4 independent 16B gathers in flight per iteration.
__global__ void attn_kernel() {
    int node = blockIdx.x * (blockDim.x >> 5) + (threadIdx.x >> 5);
    if (node >= NN) return;
    int lane = threadIdx.x & 31;
    float4 qv = ((const float4*)(g_q + (size_t)node * DD))[lane];
    float s = 0.f;
    float4 acc = make_float4(0.f, 0.f, 0.f, 0.f);
    int e0 = g_off[node], e1 = g_off[node + 1];
    int e = e0;
    for (; e + 2 <= e1; e += 2) {
        int s0 = g_csr[e], s1 = g_csr[e + 1];
        float4 k0 = ((const float4*)(g_k + (size_t)s0 * DD))[lane];
        float4 v0 = ((const float4*)(g_v + (size_t)s0 * DD))[lane];
        float4 k1 = ((const float4*)(g_k + (size_t)s1 * DD))[lane];
        float4 v1 = ((const float4*)(g_v + (size_t)s1 * DD))[lane];
        float p0 = qv.x * k0.x + qv.y * k0.y + qv.z * k0.z + qv.w * k0.w;
        float p1 = qv.x * k1.x + qv.y * k1.y + qv.z * k1.z + qv.w * k1.w;
        p0 += __shfl_xor_sync(0xFFFFFFFFu, p0, 1);
        p0 += __shfl_xor_sync(0xFFFFFFFFu, p0, 2);
        p1 += __shfl_xor_sync(0xFFFFFFFFu, p1, 1);
        p1 += __shfl_xor_sync(0xFFFFFFFFu, p1, 2);
        float w0 = __expf(p0 * 0.25f);
        float w1 = __expf(p1 * 0.25f);
        s += w0 + w1;
        acc.x += w0 * v0.x + w1 * v1.x;
        acc.y += w0 * v0.y + w1 * v1.y;
        acc.z += w0 * v0.z + w1 * v1.z;
        acc.w += w0 * v0.w + w1 * v1.w;
    }
    if (e < e1) {
        int s0 = g_csr[e];
        float4 k0 = ((const float4*)(g_k + (size_t)s0 * DD))[lane];
        float4 v0 = ((const float4*)(g_v + (size_t)s0 * DD))[lane];
        float p0 = qv.x * k0.x + qv.y * k0.y + qv.z * k0.z + qv.w * k0.w;
        p0 += __shfl_xor_sync(0xFFFFFFFFu, p0, 1);
        p0 += __shfl_xor_sync(0xFFFFFFFFu, p0, 2);
        float w0 = __expf(p0 * 0.25f);
        s += w0;
        acc.x += w0 * v0.x; acc.y += w0 * v0.y;
        acc.z += w0 * v0.z; acc.w += w0 * v0.w;
    }
    float inv = (s > 0.f) ? 1.f / s : 0.f;
    float4 o = make_float4(acc.x * inv, acc.y * inv, acc.z * inv, acc.w * inv);
    ((float4*)(g_agg + (size_t)node * DD))[lane] = o;
}

// ---------------- host-side launch -----------------------------------------
static inline void run_gemm(int bias, int relu, const float* A, const float* B,
                            const float* bp, float* C, int M, int N, int K) {
    dim3 grid((N + 127) / 128, (M + 127) / 128);
    if (bias && relu)
        tf32gemm_kernel<1, 1><<<grid, 256, GEMM_SMEM_BYTES>>>(A, B, bp, C, M, N, K);
    else if (bias)
        tf32gemm_kernel<1, 0><<<grid, 256, GEMM_SMEM_BYTES>>>(A, B, bp, C, M, N, K);
    else
        tf32gemm_kernel<0, 0><<<grid, 256, GEMM_SMEM_BYTES>>>(A, B, bp, C, M, N, K);
}

extern "C" void kernel_launch(void* const* d_in, const int* in_sizes, int n_in,
                              void* d_out, int out_size) {
    const float* X        = (const float*)d_in[0];
    const int*   ei       = (const int*)d_in[1];
    const float* emb_w    = (const float*)d_in[2];
    const float* emb_b    = (const float*)d_in[3];
    const float* emb_ln_g = (const float*)d_in[4];
    const float* emb_ln_b = (const float*)d_in[5];
    const float* Wq       = (const float*)d_in[6];
    const float* Wk       = (const float*)d_in[7];
    const float* Wv       = (const float*)d_in[8];
    const float* Wo       = (const float*)d_in[9];
    const float* ln_g     = (const float*)d_in[10];
    const float* ln_b     = (const float*)d_in[11];
    const float* f1_w     = (const float*)d_in[12];
    const float* f1_b     = (const float*)d_in[13];
    const float* f2_w     = (const float*)d_in[14];
    const float* f2_b     = (const float*)d_in[15];
    const float* f3_w     = (const float*)d_in[16];
    const float* f3_b     = (const float*)d_in[17];
    float* out = (float*)d_out;

    const int* src = ei;
    const int* dst = ei + EE;

    // allow >48KB dynamic smem for the GEMM variants (idempotent, not captured)
    cudaFuncSetAttribute(tf32gemm_kernel<1, 1>,
                         cudaFuncAttributeMaxDynamicSharedMemorySize, GEMM_SMEM_BYTES);
    cudaFuncSetAttribute(tf32gemm_kernel<1, 0>,
                         cudaFuncAttributeMaxDynamicSharedMemorySize, GEMM_SMEM_BYTES);
    cudaFuncSetAttribute(tf32gemm_kernel<0, 0>,
                         cudaFuncAttributeMaxDynamicSharedMemorySize, GEMM_SMEM_BYTES);

    float *p_h, *p_q, *p_k, *p_v, *p_agg, *p_t, *p_t2;
    cudaGetSymbolAddress((void**)&p_h,   g_h);
    cudaGetSymbolAddress((void**)&p_q,   g_q);
    cudaGetSymbolAddress((void**)&p_k,   g_k);
    cudaGetSymbolAddress((void**)&p_v,   g_v);
    cudaGetSymbolAddress((void**)&p_agg, g_agg);
    cudaGetSymbolAddress((void**)&p_t,   g_t);
    cudaGetSymbolAddress((void**)&p_t2,  g_t2);

    // ---- CSR build (by dst) ----
    zero_deg_kernel<<<(NN + 255) / 256, 256>>>();
    count_deg_kernel<<<(EE + 255) / 256, 256>>>(dst);
    scan_kernel<<<1, 1024>>>();
    scatter_kernel<<<(EE + 255) / 256, 256>>>(src, dst);

    // ---- embedding: relu(X @ emb_w + b) -> LN -> h ----
    run_gemm(1, 1, X, emb_w, emb_b, p_t, NN, DD, DIN);
    ln_kernel<0><<<(NN + 7) / 8, 256>>>(p_t, nullptr, emb_ln_g, emb_ln_b, p_h);

    // ---- layers ----
    for (int l = 0; l < LL; l++) {
        const float* wq = Wq + (size_t)l * DD * DD;
        const float* wk = Wk + (size_t)l * DD * DD;
        const float* wv = Wv + (size_t)l * DD * DD;
        const float* wo = Wo + (size_t)l * DD * DD;
        run_gemm(0, 0, p_h, wq, nullptr, p_q, NN, DD, DD);
        run_gemm(0, 0, p_h, wk, nullptr, p_k, NN, DD, DD);
        run_gemm(0, 0, p_h, wv, nullptr, p_v, NN, DD, DD);
        attn_kernel<<<(NN + 7) / 8, 256>>>();
        run_gemm(0, 0, p_agg, wo, nullptr, p_t, NN, DD, DD);
        ln_kernel<1><<<(NN + 7) / 8, 256>>>(p_t, p_h, ln_g + l * DD, ln_b + l * DD, p_h);
    }

    // ---- MLP head ----
    run_gemm(1, 1, p_h,  f1_w, f1_b, p_t,  NN, 512, DD);
    run_gemm(1, 1, p_t,  f2_w, f2_b, p_t2, NN, 512, 512);
    run_gemm(1, 0, p_t2, f3_w, f3_b, out,  NN, NCC, 512);
}

// round 9
// speedup vs baseline: 2.6115x; 1.0272x over previous
#include <cuda_runtime.h>
#include <math.h>
#include <math_constants.h>

#define NN 50000
#define EE 640000
#define DIN 256
#define DD 128
#define HH 8
#define NCC 47
#define LL 3

// ---------------- scratch (static device allocations; no runtime alloc) ----
__device__ float g_h[NN * DD];
__device__ float g_agg[NN * DD];
__device__ float g_t[NN * 512];       // qkv [N,384] per layer; also ff1 [N,512]
__device__ float g_t2[NN * 512];      // agg@Wo [N,128]; ff2 [N,512]
__device__ float g_wqkv[LL * DD * 384];
__device__ int   g_deg[NN];
__device__ int   g_off[NN + 1];
__device__ int   g_cur[NN];
__device__ int   g_csr[EE];

// ---------------- CSR build ------------------------------------------------
__global__ void zero_deg_kernel() {
    int i = blockIdx.x * blockDim.x + threadIdx.x;
    if (i < NN) g_deg[i] = 0;
}

__global__ void count_deg_kernel(const int* __restrict__ dst) {
    int e = blockIdx.x * blockDim.x + threadIdx.x;
    if (e < EE) atomicAdd(&g_deg[dst[e]], 1);
}

__global__ void scan_kernel() {
    __shared__ int wsum[32];
    __shared__ int carry_s;
    int t = threadIdx.x, lane = t & 31, wid = t >> 5;
    if (t == 0) carry_s = 0;
    __syncthreads();
    for (int base = 0; base < NN; base += 1024) {
        int i = base + t;
        int val = (i < NN) ? g_deg[i] : 0;
        int incl = val;
        #pragma unroll
        for (int o = 1; o < 32; o <<= 1) {
            int x = __shfl_up_sync(0xFFFFFFFFu, incl, o);
            if (lane >= o) incl += x;
        }
        if (lane == 31) wsum[wid] = incl;
        __syncthreads();
        if (wid == 0) {
            int wv = wsum[lane];
            int wincl = wv;
            #pragma unroll
            for (int o = 1; o < 32; o <<= 1) {
                int x = __shfl_up_sync(0xFFFFFFFFu, wincl, o);
                if (lane >= o) wincl += x;
            }
            wsum[lane] = wincl - wv;
        }
        __syncthreads();
        int carry = carry_s;
        int excl = carry + wsum[wid] + incl - val;
        if (i < NN) { g_off[i] = excl; g_cur[i] = excl; }
        __syncthreads();
        if (t == 1023) carry_s = carry + wsum[31] + incl;
        __syncthreads();
    }
    if (threadIdx.x == 0) g_off[NN] = carry_s;
}

__global__ void scatter_kernel(const int* __restrict__ src, const int* __restrict__ dst) {
    int e = blockIdx.x * blockDim.x + threadIdx.x;
    if (e < EE) {
        int d = dst[e];
        int pos = atomicAdd(&g_cur[d], 1);
        g_csr[pos] = src[e];
    }
}

// ---------------- pack Wq|Wk|Wv -> [L][128][384] ---------------------------
__global__ void pack_qkv_kernel(const float* __restrict__ Wq,
                                const float* __restrict__ Wk,
                                const float* __restrict__ Wv) {
    int i = blockIdx.x * blockDim.x + threadIdx.x;
    if (i < LL * DD * DD) {
        int l = i / (DD * DD);
        int r = (i / DD) % DD;
        int c = i % DD;
        size_t o = ((size_t)l * DD + r) * 384;
        g_wqkv[o + c]       = Wq[i];
        g_wqkv[o + 128 + c] = Wk[i];
        g_wqkv[o + 256 + c] = Wv[i];
    }
}

// ---------------- TF32 tensor-core GEMM (double-buffered) ------------------
__device__ __forceinline__ unsigned f2tf(float f) {
    unsigned u;
    asm("cvt.rna.tf32.f32 %0, %1;" : "=r"(u) : "f"(f));
    return u;
}

#define GEMM_SMEM_BYTES (2 * 2 * 16 * 136 * 4)

template <int BIAS, int RELU>
__global__ void __launch_bounds__(256)
tf32gemm_kernel(const float* __restrict__ A, const float* __restrict__ B,
                const float* __restrict__ bias, float* __restrict__ C,
                int M, int N, int K) {
    extern __shared__ unsigned sm[];
    unsigned (*As)[16][136] = (unsigned (*)[16][136])sm;
    unsigned (*Bs)[16][136] = (unsigned (*)[16][136])(sm + 2 * 16 * 136);

    int tid = threadIdx.x, lane = tid & 31, wid = tid >> 5;
    int row0 = blockIdx.y * 128, col0 = blockIdx.x * 128;
    int wm = (wid & 3) * 32, wn = (wid >> 2) * 64;
    int g = lane >> 2, c = lane & 3;

    int aRow = tid >> 1, aSeg = tid & 1;
    int bRow = tid >> 5;
    int gr = row0 + aRow;
    int gc = col0 + lane * 4;

    const bool nVec = ((N & 127) == 0);
    const bool nEven = ((N & 1) == 0);

    float acc[2][8][4];
    #pragma unroll
    for (int i = 0; i < 2; i++)
        #pragma unroll
        for (int j = 0; j < 8; j++)
            #pragma unroll
            for (int r = 0; r < 4; r++) acc[i][j][r] = 0.f;

    float4 pa0, pa1, pb0, pb1;

    auto fetch = [&](int k0) {
        pa0 = make_float4(0.f, 0.f, 0.f, 0.f); pa1 = pa0;
        if (gr < M) {
            const float* ap = A + (size_t)gr * K + k0 + aSeg * 8;
            pa0 = ((const float4*)ap)[0];
            pa1 = ((const float4*)ap)[1];
        }
        const float* bp0 = B + (size_t)(k0 + bRow) * N + gc;
        const float* bp1 = B + (size_t)(k0 + bRow + 8) * N + gc;
        if (nVec) {
            pb0 = *(const float4*)bp0;
            pb1 = *(const float4*)bp1;
        } else {
            pb0.x = (gc + 0 < N) ? bp0[0] : 0.f;
            pb0.y = (gc + 1 < N) ? bp0[1] : 0.f;
            pb0.z = (gc + 2 < N) ? bp0[2] : 0.f;
            pb0.w = (gc + 3 < N) ? bp0[3] : 0.f;
            pb1.x = (gc + 0 < N) ? bp1[0] : 0.f;
            pb1.y = (gc + 1 < N) ? bp1[1] : 0.f;
            pb1.z = (gc + 2 < N) ? bp1[2] : 0.f;
            pb1.w = (gc + 3 < N) ? bp1[3] : 0.f;
        }
    };
    auto stage = [&](int s) {
        int kb = aSeg * 8;
        As[s][kb + 0][aRow] = f2tf(pa0.x);
        As[s][kb + 1][aRow] = f2tf(pa0.y);
        As[s][kb + 2][aRow] = f2tf(pa0.z);
        As[s][kb + 3][aRow] = f2tf(pa0.w);
        As[s][kb + 4][aRow] = f2tf(pa1.x);
        As[s][kb + 5][aRow] = f2tf(pa1.y);
        As[s][kb + 6][aRow] = f2tf(pa1.z);
        As[s][kb + 7][aRow] = f2tf(pa1.w);
        Bs[s][bRow][lane * 4 + 0] = f2tf(pb0.x);
        Bs[s][bRow][lane * 4 + 1] = f2tf(pb0.y);
        Bs[s][bRow][lane * 4 + 2] = f2tf(pb0.z);
        Bs[s][bRow][lane * 4 + 3] = f2tf(pb0.w);
        Bs[s][bRow + 8][lane * 4 + 0] = f2tf(pb1.x);
        Bs[s][bRow + 8][lane * 4 + 1] = f2tf(pb1.y);
        Bs[s][bRow + 8][lane * 4 + 2] = f2tf(pb1.z);
        Bs[s][bRow + 8][lane * 4 + 3] = f2tf(pb1.w);
    };

    fetch(0);
    stage(0);
    __syncthreads();

    int s = 0;
    for (int k0 = 0; k0 < K; k0 += 16) {
        bool hasNext = (k0 + 16) < K;
        if (hasNext) fetch(k0 + 16);

        #pragma unroll
        for (int ks = 0; ks < 2; ks++) {
            int kb = ks * 8;
            unsigned a[2][4];
            #pragma unroll
            for (int i = 0; i < 2; i++) {
                int m = wm + 16 * i + g;
                a[i][0] = As[s][kb + c][m];
                a[i][1] = As[s][kb + c][m + 8];
                a[i][2] = As[s][kb + c + 4][m];
                a[i][3] = As[s][kb + c + 4][m + 8];
            }
            #pragma unroll
            for (int j = 0; j < 8; j++) {
                unsigned b0 = Bs[s][kb + c][wn + 8 * j + g];
                unsigned b1 = Bs[s][kb + c + 4][wn + 8 * j + g];
                #pragma unroll
                for (int i = 0; i < 2; i++) {
                    asm volatile(
                        "mma.sync.aligned.m16n8k8.row.col.f32.tf32.tf32.f32 "
                        "{%0,%1,%2,%3}, {%4,%5,%6,%7}, {%8,%9}, {%0,%1,%2,%3};"
                        : "+f"(acc[i][j][0]), "+f"(acc[i][j][1]),
                          "+f"(acc[i][j][2]), "+f"(acc[i][j][3])
                        : "r"(a[i][0]), "r"(a[i][1]), "r"(a[i][2]), "r"(a[i][3]),
                          "r"(b0), "r"(b1));
                }
            }
        }

        if (hasNext) {
            stage(s ^ 1);
            __syncthreads();
            s ^= 1;
        }
    }

    // epilogue
    #pragma unroll
    for (int i = 0; i < 2; i++) {
        int r = row0 + wm + 16 * i + g;
        #pragma unroll
        for (int j = 0; j < 8; j++) {
            int cc = col0 + wn + 8 * j + 2 * c;
            #pragma unroll
            for (int hh = 0; hh < 2; hh++) {
                int rr = r + hh * 8;
                if (rr < M) {
                    float v0 = acc[i][j][hh * 2 + 0];
                    float v1 = acc[i][j][hh * 2 + 1];
                    float* cp = C + (size_t)rr * N + cc;
                    if (nEven) {
                        if (cc + 1 < N) {
                            if (BIAS) { v0 += bias[cc]; v1 += bias[cc + 1]; }
                            if (RELU) { v0 = fmaxf(v0, 0.f); v1 = fmaxf(v1, 0.f); }
                            *(float2*)cp = make_float2(v0, v1);
                        } else if (cc < N) {
                            if (BIAS) v0 += bias[cc];
                            if (RELU) v0 = fmaxf(v0, 0.f);
                            cp[0] = v0;
                        }
                    } else {
                        if (cc < N) {
                            if (BIAS) v0 += bias[cc];
                            if (RELU) v0 = fmaxf(v0, 0.f);
                            cp[0] = v0;
                        }
                        if (cc + 1 < N) {
                            if (BIAS) v1 += bias[cc + 1];
                            if (RELU) v1 = fmaxf(v1, 0.f);
                            cp[1] = v1;
                        }
                    }
                }
            }
        }
    }
}

// ---------------- LayerNorm over D=128 (warp per node) ---------------------
template <int RESID>
__global__ void ln_kernel(const float* __restrict__ X, const float* __restrict__ R,
                          const float* __restrict__ g, const float* __restrict__ b,
                          float* __restrict__ out) {
    int node = blockIdx.x * (blockDim.x >> 5) + (threadIdx.x >> 5);
    if (node >= NN) return;
    int lane = threadIdx.x & 31;
    float4 x = ((const float4*)(X + (size_t)node * DD))[lane];
    if (RESID) {
        float4 r = ((const float4*)(R + (size_t)node * DD))[lane];
        x.x += r.x; x.y += r.y; x.z += r.z; x.w += r.w;
    }
    float s = x.x + x.y + x.z + x.w;
    #pragma unroll
    for (int o = 16; o; o >>= 1) s += __shfl_xor_sync(0xFFFFFFFFu, s, o);
    float mu = s * (1.f / 128.f);
    float dx = x.x - mu, dy = x.y - mu, dz = x.z - mu, dw = x.w - mu;
    float v = dx * dx + dy * dy + dz * dz + dw * dw;
    #pragma unroll
    for (int o = 16; o; o >>= 1) v += __shfl_xor_sync(0xFFFFFFFFu, v, o);
    float rstd = rsqrtf(v * (1.f / 128.f) + 1e-5f);
    float4 gg = ((const float4*)g)[lane];
    float4 bb = ((const float4*)b)[lane];
    float4 o4;
    o4.x = dx * rstd * gg.x + bb.x;
    o4.y = dy * rstd * gg.y + bb.y;
    o4.z = dz * rstd * gg.z + bb.z;
    o4.w = dw * rstd * gg.w + bb.w;
    ((float4*)(out + (size_t)node * DD))[lane] = o4;
}

// ---------------- attention + aggregation (warp per dst node) --------------
// qkv interleaved [node][384]: q cols 0-127, k 128-255, v 256-383.
// k and v for an edge are one contiguous 1KB region -> better L2 locality.
__global__ void attn_kernel() {
    int node = blockIdx.x * (blockDim.x >> 5) + (threadIdx.x >> 5);
    if (node >= NN) return;
    int lane = threadIdx.x & 31;
    const float* qkv = g_t;
    float4 qv = ((const float4*)(qkv + (size_t)node * 384))[lane];
    float s = 0.f;
    float4 acc = make_float4(0.f, 0.f, 0.f, 0.f);
    int e0 = g_off[node], e1 = g_off[node + 1];
    int e = e0;
    for (; e + 2 <= e1; e += 2) {
        const float* b0p = qkv + (size_t)g_csr[e] * 384;
        const float* b1p = qkv + (size_t)g_csr[e + 1] * 384;
        float4 k0 = ((const float4*)(b0p + 128))[lane];
        float4 v0 = ((const float4*)(b0p + 256))[lane];
        float4 k1 = ((const float4*)(b1p + 128))[lane];
        float4 v1 = ((const float4*)(b1p + 256))[lane];
        float p0 = qv.x * k0.x + qv.y * k0.y + qv.z * k0.z + qv.w * k0.w;
        float p1 = qv.x * k1.x + qv.y * k1.y + qv.z * k1.z + qv.w * k1.w;
        p0 += __shfl_xor_sync(0xFFFFFFFFu, p0, 1);
        p0 += __shfl_xor_sync(0xFFFFFFFFu, p0, 2);
        p1 += __shfl_xor_sync(0xFFFFFFFFu, p1, 1);
        p1 += __shfl_xor_sync(0xFFFFFFFFu, p1, 2);
        float w0 = __expf(p0 * 0.25f);
        float w1 = __expf(p1 * 0.25f);
        s += w0 + w1;
        acc.x += w0 * v0.x + w1 * v1.x;
        acc.y += w0 * v0.y + w1 * v1.y;
        acc.z += w0 * v0.z + w1 * v1.z;
        acc.w += w0 * v0.w + w1 * v1.w;
    }
    if (e < e1) {
        const float* b0p = qkv + (size_t)g_csr[e] * 384;
        float4 k0 = ((const float4*)(b0p + 128))[lane];
        float4 v0 = ((const float4*)(b0p + 256))[lane];
        float p0 = qv.x * k0.x + qv.y * k0.y + qv.z * k0.z + qv.w * k0.w;
        p0 += __shfl_xor_sync(0xFFFFFFFFu, p0, 1);
        p0 += __shfl_xor_sync(0xFFFFFFFFu, p0, 2);
        float w0 = __expf(p0 * 0.25f);
        s += w0;
        acc.x += w0 * v0.x; acc.y += w0 * v0.y;
        acc.z += w0 * v0.z; acc.w += w0 * v0.w;
    }
    float inv = (s > 0.f) ? 1.f / s : 0.f;
    float4 o = make_float4(acc.x * inv, acc.y * inv, acc.z * inv, acc.w * inv);
    ((float4*)(g_agg + (size_t)node * DD))[lane] = o;
}

// ---------------- host-side launch -----------------------------------------
static inline void run_gemm(int bias, int relu, const float* A, const float* B,
                            const float* bp, float* C, int M, int N, int K) {
    dim3 grid((N + 127) / 128, (M + 127) / 128);
    if (bias && relu)
        tf32gemm_kernel<1, 1><<<grid, 256, GEMM_SMEM_BYTES>>>(A, B, bp, C, M, N, K);
    else if (bias)
        tf32gemm_kernel<1, 0><<<grid, 256, GEMM_SMEM_BYTES>>>(A, B, bp, C, M, N, K);
    else
        tf32gemm_kernel<0, 0><<<grid, 256, GEMM_SMEM_BYTES>>>(A, B, bp, C, M, N, K);
}

extern "C" void kernel_launch(void* const* d_in, const int* in_sizes, int n_in,
                              void* d_out, int out_size) {
    const float* X        = (const float*)d_in[0];
    const int*   ei       = (const int*)d_in[1];
    const float* emb_w    = (const float*)d_in[2];
    const float* emb_b    = (const float*)d_in[3];
    const float* emb_ln_g = (const float*)d_in[4];
    const float* emb_ln_b = (const float*)d_in[5];
    const float* Wq       = (const float*)d_in[6];
    const float* Wk       = (const float*)d_in[7];
    const float* Wv       = (const float*)d_in[8];
    const float* Wo       = (const float*)d_in[9];
    const float* ln_g     = (const float*)d_in[10];
    const float* ln_b     = (const float*)d_in[11];
    const float* f1_w     = (const float*)d_in[12];
    const float* f1_b     = (const float*)d_in[13];
    const float* f2_w     = (const float*)d_in[14];
    const float* f2_b     = (const float*)d_in[15];
    const float* f3_w     = (const float*)d_in[16];
    const float* f3_b     = (const float*)d_in[17];
    float* out = (float*)d_out;

    const int* src = ei;
    const int* dst = ei + EE;

    cudaFuncSetAttribute(tf32gemm_kernel<1, 1>,
                         cudaFuncAttributeMaxDynamicSharedMemorySize, GEMM_SMEM_BYTES);
    cudaFuncSetAttribute(tf32gemm_kernel<1, 0>,
                         cudaFuncAttributeMaxDynamicSharedMemorySize, GEMM_SMEM_BYTES);
    cudaFuncSetAttribute(tf32gemm_kernel<0, 0>,
                         cudaFuncAttributeMaxDynamicSharedMemorySize, GEMM_SMEM_BYTES);

    float *p_h, *p_agg, *p_t, *p_t2, *p_wqkv;
    cudaGetSymbolAddress((void**)&p_h,    g_h);
    cudaGetSymbolAddress((void**)&p_agg,  g_agg);
    cudaGetSymbolAddress((void**)&p_t,    g_t);
    cudaGetSymbolAddress((void**)&p_t2,   g_t2);
    cudaGetSymbolAddress((void**)&p_wqkv, g_wqkv);

    // ---- CSR build (by dst) + weight packing ----
    zero_deg_kernel<<<(NN + 255) / 256, 256>>>();
    count_deg_kernel<<<(EE + 255) / 256, 256>>>(dst);
    scan_kernel<<<1, 1024>>>();
    scatter_kernel<<<(EE + 255) / 256, 256>>>(src, dst);
    pack_qkv_kernel<<<(LL * DD * DD + 255) / 256, 256>>>(Wq, Wk, Wv);

    // ---- embedding: relu(X @ emb_w + b) -> LN -> h ----
    run_gemm(1, 1, X, emb_w, emb_b, p_t2, NN, DD, DIN);
    ln_kernel<0><<<(NN + 7) / 8, 256>>>(p_t2, nullptr, emb_ln_g, emb_ln_b, p_h);

    // ---- layers ----
    for (int l = 0; l < LL; l++) {
        const float* wo = Wo + (size_t)l * DD * DD;
        // fused qkv: [N,384] interleaved
        run_gemm(0, 0, p_h, p_wqkv + (size_t)l * DD * 384, nullptr, p_t, NN, 384, DD);
        attn_kernel<<<(NN + 7) / 8, 256>>>();
        run_gemm(0, 0, p_agg, wo, nullptr, p_t2, NN, DD, DD);
        ln_kernel<1><<<(NN + 7) / 8, 256>>>(p_t2, p_h, ln_g + l * DD, ln_b + l * DD, p_h);
    }

    // ---- MLP head ----
    run_gemm(1, 1, p_h,  f1_w, f1_b, p_t,  NN, 512, DD);
    run_gemm(1, 1, p_t,  f2_w, f2_b, p_t2, NN, 512, 512);
    run_gemm(1, 0, p_t2, f3_w, f3_b, out,  NN, NCC, 512);
}